// round 2
// baseline (speedup 1.0000x reference)
#include <cuda_runtime.h>
#include <cuda_bf16.h>
#include <cstddef>

// ---------------- problem constants ----------------
#define NN 20000
#define EE 240000
#define GG 128
#define F_IN 128
#define EMB 256
#define HH 2
#define HC 512          // H*EMB
#define DENSE 512
#define NCLS 10

// ---------------- scratch (device globals; no allocation) ----------------
#define OFF_H     0                         // [N,512]
#define OFF_GAT   (OFF_H   + NN*512)        // [N,512]
#define OFF_X     (OFF_GAT + NN*512)        // [N,256]
#define OFF_ALS   (OFF_X   + NN*256)        // [N,2]
#define OFF_ALD   (OFF_ALS + NN*2)          // [N,2]
#define OFF_POOL  (OFF_ALD + NN*2)          // [G,512] accumulated reps
#define OFF_DENSE (OFF_POOL + GG*512)       // [G,512]
#define FBUF_SZ   (OFF_DENSE + GG*512)

__device__ float g_fbuf[FBUF_SZ];

#define IOFF_DEG    0
#define IOFF_ROWS   (IOFF_DEG + NN)         // N+1
#define IOFF_WP     (IOFF_ROWS + NN + 1)    // N+1
#define IOFF_CSR    (IOFF_WP + NN + 1)      // E+N
#define IOFF_GSTART (IOFF_CSR + EE + NN)    // G+1
#define IBUF_SZ     (IOFF_GSTART + GG + 1)

__device__ int g_ibuf[IBUF_SZ];

// ---------------- init: deg=1 (self loop), zero pooled accumulator ----------------
__global__ void k_init(int* deg, float* pool) {
    int i = blockIdx.x * blockDim.x + threadIdx.x;
    if (i < NN) deg[i] = 1;
    if (i < GG * 512) pool[i] = 0.f;
}

// count in-degrees of real edges
__global__ void k_count(const int* __restrict__ ei, int* deg) {
    int e = blockIdx.x * blockDim.x + threadIdx.x;
    if (e < EE) atomicAdd(&deg[ei[EE + e]], 1);
}

// exclusive scan of deg[0..N) -> rows[0..N], single block of 1024
#define SCAN_T 1024
__global__ void k_scan(const int* __restrict__ deg, int* rows) {
    __shared__ int sh[SCAN_T];
    int tid = threadIdx.x;
    const int items = (NN + SCAN_T - 1) / SCAN_T;
    int start = tid * items;
    int local = 0;
    for (int i = 0; i < items; i++) {
        int idx = start + i;
        if (idx < NN) local += deg[idx];
    }
    sh[tid] = local;
    __syncthreads();
    for (int d = 1; d < SCAN_T; d <<= 1) {
        int v = (tid >= d) ? sh[tid - d] : 0;
        __syncthreads();
        sh[tid] += v;
        __syncthreads();
    }
    int run = sh[tid] - local;  // exclusive offset
    for (int i = 0; i < items; i++) {
        int idx = start + i;
        if (idx < NN) { rows[idx] = run; run += deg[idx]; }
    }
    if (tid == SCAN_T - 1) rows[NN] = sh[SCAN_T - 1];
}

__global__ void k_copy_wp(const int* __restrict__ rows, int* wp) {
    int i = blockIdx.x * blockDim.x + threadIdx.x;
    if (i <= NN) wp[i] = rows[i];
}

// scatter edges (and self loops) into CSR-by-dst
__global__ void k_scatter(const int* __restrict__ ei, int* wp, int* csr) {
    int i = blockIdx.x * blockDim.x + threadIdx.x;
    if (i >= EE + NN) return;
    int s, d;
    if (i < EE) { s = ei[i]; d = ei[EE + i]; }
    else        { s = d = i - EE; }
    int pos = atomicAdd(&wp[d], 1);
    csr[pos] = s;
}

// graph boundaries from sorted batch_index
__global__ void k_gstart(const int* __restrict__ batch, int* gstart) {
    int v = blockIdx.x * blockDim.x + threadIdx.x;
    if (v >= NN) return;
    int b = batch[v];
    if (v == 0) {
        for (int g = 0; g <= b; g++) gstart[g] = 0;
    } else {
        int bp = batch[v - 1];
        for (int g = bp + 1; g <= b; g++) gstart[g] = v;
    }
    if (v == NN - 1) {
        for (int g = b + 1; g <= GG; g++) gstart[g] = NN;
    }
}

// ---------------- tiled fp32 GEMM: C[M,Nc] = A[M,K]*B[K,Nc] (+bias)(+relu) ----------
#define BM 128
#define BN 128
#define BK 8
#define TM 8
#define TN 8
__global__ __launch_bounds__(256) void k_sgemm(
    const float* __restrict__ A, const float* __restrict__ B,
    const float* __restrict__ bias, float* __restrict__ C,
    int M, int K, int Nc, int doRelu)
{
    __shared__ float As[BK][BM];
    __shared__ float Bs[BK][BN];
    int tid = threadIdx.x;
    int ty = tid / 16, tx = tid % 16;
    int rowBase = blockIdx.y * BM;
    int colBase = blockIdx.x * BN;

    float acc[TM][TN];
#pragma unroll
    for (int i = 0; i < TM; i++)
#pragma unroll
        for (int j = 0; j < TN; j++) acc[i][j] = 0.f;

    int ar = tid >> 1;          // 0..127
    int ak = (tid & 1) * 4;     // 0 or 4
    int bk = tid >> 5;          // 0..7
    int bn = (tid & 31) * 4;    // 0..124

    for (int k0 = 0; k0 < K; k0 += BK) {
        float4 a4;
        int grow = rowBase + ar;
        if (grow < M) a4 = *(const float4*)(A + (size_t)grow * K + k0 + ak);
        else a4 = make_float4(0.f, 0.f, 0.f, 0.f);
        As[ak + 0][ar] = a4.x; As[ak + 1][ar] = a4.y;
        As[ak + 2][ar] = a4.z; As[ak + 3][ar] = a4.w;
        float4 b4 = *(const float4*)(B + (size_t)(k0 + bk) * Nc + colBase + bn);
        *(float4*)&Bs[bk][bn] = b4;
        __syncthreads();
#pragma unroll
        for (int k = 0; k < BK; k++) {
            float af[TM], bf[TN];
            *(float4*)&af[0] = *(float4*)&As[k][ty * TM];
            *(float4*)&af[4] = *(float4*)&As[k][ty * TM + 4];
            *(float4*)&bf[0] = *(float4*)&Bs[k][tx * TN];
            *(float4*)&bf[4] = *(float4*)&Bs[k][tx * TN + 4];
#pragma unroll
            for (int i = 0; i < TM; i++)
#pragma unroll
                for (int j = 0; j < TN; j++)
                    acc[i][j] += af[i] * bf[j];
        }
        __syncthreads();
    }

#pragma unroll
    for (int i = 0; i < TM; i++) {
        int r = rowBase + ty * TM + i;
        if (r >= M) continue;
#pragma unroll
        for (int j = 0; j < TN; j += 4) {
            int cidx = colBase + tx * TN + j;
            float4 v = *(float4*)&acc[i][j];
            if (bias) {
                v.x += bias[cidx]; v.y += bias[cidx + 1];
                v.z += bias[cidx + 2]; v.w += bias[cidx + 3];
            }
            if (doRelu) {
                v.x = fmaxf(v.x, 0.f); v.y = fmaxf(v.y, 0.f);
                v.z = fmaxf(v.z, 0.f); v.w = fmaxf(v.w, 0.f);
            }
            *(float4*)(C + (size_t)r * Nc + cidx) = v;
        }
    }
}

// ---------------- per-node attention logit terms ----------------
__global__ void k_al(const float* __restrict__ h, const float* __restrict__ asrc,
                     const float* __restrict__ adst, float* __restrict__ als,
                     float* __restrict__ ald)
{
    int warp = (blockIdx.x * blockDim.x + threadIdx.x) >> 5;
    int lane = threadIdx.x & 31;
    if (warp >= NN) return;
    const float* hr = h + (size_t)warp * 512;
    float s0 = 0.f, s1 = 0.f, d0 = 0.f, d1 = 0.f;
#pragma unroll
    for (int i = 0; i < 8; i++) {
        int c = i * 32 + lane;
        float h0 = hr[c], h1 = hr[256 + c];
        s0 += h0 * asrc[c];        d0 += h0 * adst[c];
        s1 += h1 * asrc[256 + c];  d1 += h1 * adst[256 + c];
    }
#pragma unroll
    for (int off = 16; off; off >>= 1) {
        s0 += __shfl_xor_sync(0xffffffffu, s0, off);
        s1 += __shfl_xor_sync(0xffffffffu, s1, off);
        d0 += __shfl_xor_sync(0xffffffffu, d0, off);
        d1 += __shfl_xor_sync(0xffffffffu, d1, off);
    }
    if (lane == 0) {
        als[warp * 2] = s0; als[warp * 2 + 1] = s1;
        ald[warp * 2] = d0; ald[warp * 2 + 1] = d1;
    }
}

// ---------------- attention softmax + aggregation (one warp per dst node) -----------
__global__ void k_attn(const float* __restrict__ h, const float* __restrict__ als,
                       const float* __restrict__ ald, const float* __restrict__ bvec,
                       const int* __restrict__ rows, const int* __restrict__ csr,
                       float* __restrict__ out)
{
    int warp = (blockIdx.x * blockDim.x + threadIdx.x) >> 5;
    int lane = threadIdx.x & 31;
    if (warp >= NN) return;
    int v = warp;
    int s0 = rows[v], s1 = rows[v + 1];
    int deg = s1 - s0;
    float ad0 = ald[v * 2], ad1 = ald[v * 2 + 1];

    // pass 1: max logit per head
    float m0 = -1e30f, m1 = -1e30f;
    for (int base = 0; base < deg; base += 32) {
        int j = base + lane;
        if (j < deg) {
            int s = csr[s0 + j];
            float t0 = als[s * 2] + ad0;     t0 = fmaxf(t0, 0.2f * t0);
            float t1 = als[s * 2 + 1] + ad1; t1 = fmaxf(t1, 0.2f * t1);
            m0 = fmaxf(m0, t0); m1 = fmaxf(m1, t1);
        }
    }
#pragma unroll
    for (int off = 16; off; off >>= 1) {
        m0 = fmaxf(m0, __shfl_xor_sync(0xffffffffu, m0, off));
        m1 = fmaxf(m1, __shfl_xor_sync(0xffffffffu, m1, off));
    }

    // pass 2: exp weights + weighted aggregation, 2 edges/iter for load MLP
    float acc[16];
#pragma unroll
    for (int k = 0; k < 16; k++) acc[k] = 0.f;
    float den0 = 0.f, den1 = 0.f;
    int j = 0;
    for (; j + 2 <= deg; j += 2) {
        int sa = csr[s0 + j];
        int sb = csr[s0 + j + 1];
        float ta0 = als[sa * 2] + ad0;     ta0 = fmaxf(ta0, 0.2f * ta0);
        float ta1 = als[sa * 2 + 1] + ad1; ta1 = fmaxf(ta1, 0.2f * ta1);
        float tb0 = als[sb * 2] + ad0;     tb0 = fmaxf(tb0, 0.2f * tb0);
        float tb1 = als[sb * 2 + 1] + ad1; tb1 = fmaxf(tb1, 0.2f * tb1);
        float wa0 = __expf(ta0 - m0), wa1 = __expf(ta1 - m1);
        float wb0 = __expf(tb0 - m0), wb1 = __expf(tb1 - m1);
        den0 += wa0 + wb0; den1 += wa1 + wb1;
        const float* ha = h + (size_t)sa * 512 + lane;
        const float* hb = h + (size_t)sb * 512 + lane;
#pragma unroll
        for (int k = 0; k < 16; k++) {
            float va = ha[k * 32];
            float vb = hb[k * 32];
            acc[k] += (k < 8 ? wa0 : wa1) * va + (k < 8 ? wb0 : wb1) * vb;
        }
    }
    for (; j < deg; j++) {
        int s = csr[s0 + j];
        float t0 = als[s * 2] + ad0;     t0 = fmaxf(t0, 0.2f * t0);
        float t1 = als[s * 2 + 1] + ad1; t1 = fmaxf(t1, 0.2f * t1);
        float w0 = __expf(t0 - m0), w1 = __expf(t1 - m1);
        den0 += w0; den1 += w1;
        const float* hr = h + (size_t)s * 512 + lane;
#pragma unroll
        for (int k = 0; k < 16; k++)
            acc[k] += (k < 8 ? w0 : w1) * hr[k * 32];
    }
    float r0 = 1.0f / den0, r1 = 1.0f / den1;
    float* orow = out + (size_t)v * 512 + lane;
#pragma unroll
    for (int k = 0; k < 16; k++) {
        float val = acc[k] * (k < 8 ? r0 : r1) + bvec[k * 32 + lane];
        orow[k * 32] = fmaxf(val, 0.f);   // fused relu (post-GAT)
    }
}

// ---------------- pooling: per-graph max + mean, accumulated across layers ----------
__global__ void k_pool(const float* __restrict__ x, const int* __restrict__ gstart,
                       float* __restrict__ gacc)
{
    int g = blockIdx.x;
    int c = threadIdx.x;   // 256
    int s = gstart[g], e = gstart[g + 1];
    float mx = 0.f, sm = 0.f;   // post-relu values are >= 0
    int v = s;
    for (; v + 2 <= e; v += 2) {
        float a = x[(size_t)v * 256 + c];
        float b = x[(size_t)(v + 1) * 256 + c];
        sm += a + b; mx = fmaxf(mx, fmaxf(a, b));
    }
    if (v < e) {
        float a = x[(size_t)v * 256 + c];
        sm += a; mx = fmaxf(mx, a);
    }
    int cnt = e - s;
    float mean = (cnt > 0) ? sm / (float)cnt : 0.f;
    gacc[g * 512 + c]       += mx;
    gacc[g * 512 + 256 + c] += mean;
}

// ---------------- final tiny linear: [G,512] @ [512,10] + b ----------------
__global__ void k_line2(const float* __restrict__ gd, const float* __restrict__ W,
                        const float* __restrict__ b, float* __restrict__ out)
{
    __shared__ float sh[512];
    int g = blockIdx.x;
    for (int i = threadIdx.x; i < 512; i += blockDim.x) sh[i] = gd[g * 512 + i];
    __syncthreads();
    if (threadIdx.x < NCLS) {
        float acc = b[threadIdx.x];
        for (int k = 0; k < 512; k++) acc += sh[k] * W[k * NCLS + threadIdx.x];
        out[g * NCLS + threadIdx.x] = acc;
    }
}

// ---------------- host orchestration ----------------
extern "C" void kernel_launch(void* const* d_in, const int* in_sizes, int n_in,
                              void* d_out, int out_size)
{
    const float* x_in  = (const float*)d_in[0];
    const int*   ei    = (const int*)d_in[1];
    const int*   batch = (const int*)d_in[2];
    const float* attW[3]  = {(const float*)d_in[3],  (const float*)d_in[9],  (const float*)d_in[15]};
    const float* asrc[3]  = {(const float*)d_in[4],  (const float*)d_in[10], (const float*)d_in[16]};
    const float* adst[3]  = {(const float*)d_in[5],  (const float*)d_in[11], (const float*)d_in[17]};
    const float* attb[3]  = {(const float*)d_in[6],  (const float*)d_in[12], (const float*)d_in[18]};
    const float* linW[3]  = {(const float*)d_in[7],  (const float*)d_in[13], (const float*)d_in[19]};
    const float* linb[3]  = {(const float*)d_in[8],  (const float*)d_in[14], (const float*)d_in[20]};
    const float* line1W = (const float*)d_in[21];
    const float* line1b = (const float*)d_in[22];
    const float* line2W = (const float*)d_in[23];
    const float* line2b = (const float*)d_in[24];
    float* out = (float*)d_out;

    // cache symbol addresses on first call (deterministic; avoids any non-launch
    // API inside the captured region on subsequent calls)
    static float* fbuf = nullptr;
    static int*   ibuf = nullptr;
    if (!fbuf) {
        cudaGetSymbolAddress((void**)&fbuf, g_fbuf);
        cudaGetSymbolAddress((void**)&ibuf, g_ibuf);
    }

    float* bh    = fbuf + OFF_H;
    float* bgat  = fbuf + OFF_GAT;
    float* bx    = fbuf + OFF_X;
    float* bals  = fbuf + OFF_ALS;
    float* bald  = fbuf + OFF_ALD;
    float* bpool = fbuf + OFF_POOL;
    float* bdense= fbuf + OFF_DENSE;
    int* deg    = ibuf + IOFF_DEG;
    int* rows   = ibuf + IOFF_ROWS;
    int* wp     = ibuf + IOFF_WP;
    int* csr    = ibuf + IOFF_CSR;
    int* gstart = ibuf + IOFF_GSTART;

    // ---- graph preprocessing (every call; deterministic work) ----
    {
        int n = GG * 512;  // >= NN
        k_init<<<(n + 255) / 256, 256>>>(deg, bpool);
        k_count<<<(EE + 255) / 256, 256>>>(ei, deg);
        k_scan<<<1, SCAN_T>>>(deg, rows);
        k_copy_wp<<<(NN + 256) / 256, 256>>>(rows, wp);
        k_scatter<<<(EE + NN + 255) / 256, 256>>>(ei, wp, csr);
        k_gstart<<<(NN + 255) / 256, 256>>>(batch, gstart);
    }

    // ---- three GAT layers ----
    const float* xcur = x_in;
    int fin = F_IN;
    for (int i = 0; i < 3; i++) {
        // h = x @ W   [N,fin] x [fin,512]
        {
            dim3 grid(HC / BN, (NN + BM - 1) / BM);
            k_sgemm<<<grid, 256>>>(xcur, attW[i], nullptr, bh, NN, fin, HC, 0);
        }
        // per-node attention terms
        k_al<<<(NN * 32 + 255) / 256, 256>>>(bh, asrc[i], adst[i], bals, bald);
        // softmax-attention aggregation (+ bias + relu)
        k_attn<<<(NN * 32 + 255) / 256, 256>>>(bh, bals, bald, attb[i], rows, csr, bgat);
        // x = relu(gat @ lin_W + lin_b)   [N,512] x [512,256]
        {
            dim3 grid(EMB / BN, (NN + BM - 1) / BM);
            k_sgemm<<<grid, 256>>>(bgat, linW[i], linb[i], bx, NN, HC, EMB, 1);
        }
        // pooling accumulation
        k_pool<<<GG, 256>>>(bx, gstart, bpool);
        xcur = bx;
        fin = EMB;
    }

    // ---- MLP head ----
    {
        dim3 grid(DENSE / BN, (GG + BM - 1) / BM);
        k_sgemm<<<grid, 256>>>(bpool, line1W, line1b, bdense, GG, 2 * EMB, DENSE, 1);
    }
    k_line2<<<GG, 512>>>(bdense, line2W, line2b, out);
}